// round 3
// baseline (speedup 1.0000x reference)
#include <cuda_runtime.h>
#include <cuda_bf16.h>
#include <math.h>

// Problem constants
#define NND 50000
#define FF  256
#define HH  128
#define EE  800000
#define BB  64
#define TT  50

// ---------------- device scratch ----------------
__device__ float g_reduced[NND * HH];
__device__ float g_agg[NND * HH];
__device__ float g_s[NND * HH];
__device__ float g_invdeg[NND];
__device__ int   g_deg[NND];
__device__ float g_ts[BB * TT * HH];
__device__ float g_gates[BB * TT * 4 * HH];
__device__ float g_h1[BB * TT * HH];
__device__ float g_h2[BB * TT * HH];
__device__ float g_qkv[BB * TT * 3 * HH];
__device__ float g_olast[BB * HH];
__device__ float g_bias0[4 * HH];
__device__ float g_bias1[4 * HH];

__device__ __forceinline__ float sigf(float x) { return 1.0f / (1.0f + __expf(-x)); }

// ---------------- degree kernels ----------------
__global__ __launch_bounds__(256) void deg_kernel(const int* __restrict__ dst, int* __restrict__ deg, int E) {
    int i = blockIdx.x * blockDim.x + threadIdx.x;
    if (i < E) atomicAdd(&deg[dst[i]], 1);
}

__global__ __launch_bounds__(256) void invdeg_kernel(const int* __restrict__ deg, float* __restrict__ inv, int n) {
    int i = blockIdx.x * blockDim.x + threadIdx.x;
    if (i < n) inv[i] = 1.0f / (float)max(deg[i], 1);
}

// ---------------- scatter-add (one warp per edge, v4 reductions) ----------------
__global__ __launch_bounds__(256) void scatter_add_kernel(const float* __restrict__ feat,
                                   const int* __restrict__ src,
                                   const int* __restrict__ dst,
                                   float* __restrict__ agg, int E) {
    int idx = blockIdx.x * blockDim.x + threadIdx.x;
    int e = idx >> 5;
    if (e >= E) return;
    int lane = idx & 31;
    int s = __ldg(src + e);
    int d = __ldg(dst + e);
    float4 v = *(const float4*)(feat + (size_t)s * HH + lane * 4);
    float* p = agg + (size_t)d * HH + lane * 4;
    asm volatile("red.global.add.v4.f32 [%0], {%1,%2,%3,%4};"
                 :: "l"(p), "f"(v.x), "f"(v.y), "f"(v.z), "f"(v.w) : "memory");
}

// ---------------- generic NT GEMM: C = A1@B1^T (+ A2@B2^T) + bias, optional relu ----------------
__global__ __launch_bounds__(256) void gemm_nt_kernel(
                               const float* __restrict__ A1, const float* __restrict__ B1,
                               const float* __restrict__ A2, const float* __restrict__ B2,
                               const float* __restrict__ rowscale,
                               const float* __restrict__ bias,
                               float* __restrict__ C,
                               int M, int N, int Ktot, int Ksplit, int relu) {
    __shared__ float As[32][68];
    __shared__ float Bs[32][68];
    const int tid  = threadIdx.x;           // 256 threads
    const int m0   = blockIdx.x * 64;
    const int n0   = blockIdx.y * 64;
    const int lrow = tid >> 3;               // 0..31
    const int lcol = (tid & 7) << 2;         // 0..28 step 4
    const int tx   = tid & 15;
    const int ty   = tid >> 4;
    float acc[4][4];
#pragma unroll
    for (int i = 0; i < 4; i++)
#pragma unroll
        for (int j = 0; j < 4; j++) acc[i][j] = 0.0f;

    for (int k0 = 0; k0 < Ktot; k0 += 32) {
        const float* A; const float* Bm; int lda, koff; bool doScale;
        if (k0 < Ksplit) { A = A1; Bm = B1; lda = Ksplit;        koff = k0;          doScale = (rowscale != nullptr); }
        else             { A = A2; Bm = B2; lda = Ktot - Ksplit; koff = k0 - Ksplit; doScale = false; }
#pragma unroll
        for (int half = 0; half < 2; half++) {
            int r = lrow + half * 32;
            int m = m0 + r;
            float4 av = make_float4(0.f, 0.f, 0.f, 0.f);
            if (m < M) {
                av = *(const float4*)(A + (size_t)m * lda + koff + lcol);
                if (doScale) { float sc = rowscale[m]; av.x *= sc; av.y *= sc; av.z *= sc; av.w *= sc; }
            }
            As[lcol + 0][r] = av.x; As[lcol + 1][r] = av.y; As[lcol + 2][r] = av.z; As[lcol + 3][r] = av.w;
            int n = n0 + r;
            float4 bv = make_float4(0.f, 0.f, 0.f, 0.f);
            if (n < N) bv = *(const float4*)(Bm + (size_t)n * lda + koff + lcol);
            Bs[lcol + 0][r] = bv.x; Bs[lcol + 1][r] = bv.y; Bs[lcol + 2][r] = bv.z; Bs[lcol + 3][r] = bv.w;
        }
        __syncthreads();
#pragma unroll
        for (int kk = 0; kk < 32; kk++) {
            float4 a = *(const float4*)&As[kk][ty << 2];
            float4 b = *(const float4*)&Bs[kk][tx << 2];
            acc[0][0] += a.x * b.x; acc[0][1] += a.x * b.y; acc[0][2] += a.x * b.z; acc[0][3] += a.x * b.w;
            acc[1][0] += a.y * b.x; acc[1][1] += a.y * b.y; acc[1][2] += a.y * b.z; acc[1][3] += a.y * b.w;
            acc[2][0] += a.z * b.x; acc[2][1] += a.z * b.y; acc[2][2] += a.z * b.z; acc[2][3] += a.z * b.w;
            acc[3][0] += a.w * b.x; acc[3][1] += a.w * b.y; acc[3][2] += a.w * b.z; acc[3][3] += a.w * b.w;
        }
        __syncthreads();
    }
#pragma unroll
    for (int i = 0; i < 4; i++) {
        int m = m0 + (ty << 2) + i;
        if (m >= M) continue;
#pragma unroll
        for (int j = 0; j < 4; j++) {
            int n = n0 + (tx << 2) + j;
            float v = acc[i][j] + (bias ? bias[n] : 0.0f);
            if (relu) v = fmaxf(v, 0.0f);
            C[(size_t)m * N + n] = v;
        }
    }
}

// ---------------- bias combine ----------------
__global__ __launch_bounds__(256) void bias2_kernel(const float* a, const float* b, float* o, int n) {
    int i = blockIdx.x * blockDim.x + threadIdx.x;
    if (i < n) o[i] = a[i] + b[i];
}

// ---------------- LSTM recurrence (2 batch elems per CTA, 512 threads) ----------------
__global__ __launch_bounds__(512) void lstm_rec_kernel(
                                const float* __restrict__ gx,   // B*T*512, x@Wih^T + bih + bhh
                                const float* __restrict__ Whh,  // 512 x 128
                                float* __restrict__ hout) {     // B*T*128
    const int BPC = 2;
    int b0 = blockIdx.x * BPC;
    int j = threadIdx.x;  // 0..511 (gate row)
    __shared__ float sh_h[BPC][HH];
    __shared__ float sh_c[BPC][HH];
    __shared__ float sh_g[BPC][4 * HH];
    if (j < HH) {
        sh_h[0][j] = 0.f; sh_c[0][j] = 0.f;
        sh_h[1][j] = 0.f; sh_c[1][j] = 0.f;
    }
    __syncthreads();
    const float4* W4 = (const float4*)(Whh + (size_t)j * HH);
    for (int t = 0; t < TT; t++) {
        float acc0 = gx[((size_t)(b0 + 0) * TT + t) * 512 + j];
        float acc1 = gx[((size_t)(b0 + 1) * TT + t) * 512 + j];
#pragma unroll 8
        for (int k = 0; k < 32; k++) {
            float4 w  = W4[k];
            float4 h0 = ((const float4*)sh_h[0])[k];
            float4 h1 = ((const float4*)sh_h[1])[k];
            acc0 += w.x * h0.x + w.y * h0.y + w.z * h0.z + w.w * h0.w;
            acc1 += w.x * h1.x + w.y * h1.y + w.z * h1.z + w.w * h1.w;
        }
        sh_g[0][j] = acc0;
        sh_g[1][j] = acc1;
        __syncthreads();
        if (j < 2 * HH) {
            int bb = j >> 7, jj = j & 127;
            float gi = sh_g[bb][jj];
            float gf = sh_g[bb][HH + jj];
            float gg = sh_g[bb][2 * HH + jj];
            float go = sh_g[bb][3 * HH + jj];
            float c = sigf(gf) * sh_c[bb][jj] + sigf(gi) * tanhf(gg);
            sh_c[bb][jj] = c;
            float h = sigf(go) * tanhf(c);
            sh_h[bb][jj] = h;
            hout[((size_t)(b0 + bb) * TT + t) * HH + jj] = h;
        }
        __syncthreads();
    }
}

// ---------------- attention: only last query row needed ----------------
__global__ __launch_bounds__(256) void attn_last_kernel(const float* __restrict__ qkv, float* __restrict__ olast) {
    int gidx = blockIdx.x * blockDim.x + threadIdx.x;
    int w = gidx >> 5;                // 0..127 : (b, head)
    if (w >= BB * 2) return;
    int lane = threadIdx.x & 31;
    int wl = threadIdx.x >> 5;
    int b = w >> 1, h = w & 1;
    const float* base = qkv + (size_t)b * TT * 384;
    const float* q = base + 49 * 384 + h * 64;
    float q0 = q[lane], q1 = q[lane + 32];
    __shared__ float sc[8][TT];
    for (int j = 0; j < TT; j++) {
        const float* kp = base + j * 384 + 128 + h * 64;
        float p = q0 * kp[lane] + q1 * kp[lane + 32];
#pragma unroll
        for (int o = 16; o; o >>= 1) p += __shfl_down_sync(0xffffffffu, p, o);
        if (lane == 0) sc[wl][j] = p * 0.125f;   // /sqrt(64)
    }
    __syncwarp();
    float v0 = (lane < TT) ? sc[wl][lane] : -1e30f;
    float v1 = (lane + 32 < TT) ? sc[wl][lane + 32] : -1e30f;
    float mx = fmaxf(v0, v1);
#pragma unroll
    for (int o = 16; o; o >>= 1) mx = fmaxf(mx, __shfl_xor_sync(0xffffffffu, mx, o));
    float e0 = (lane < TT) ? expf(v0 - mx) : 0.f;
    float e1 = (lane + 32 < TT) ? expf(v1 - mx) : 0.f;
    float s = e0 + e1;
#pragma unroll
    for (int o = 16; o; o >>= 1) s += __shfl_xor_sync(0xffffffffu, s, o);
    float inv = 1.0f / s;
    if (lane < TT) sc[wl][lane] = e0 * inv;
    if (lane + 32 < TT) sc[wl][lane + 32] = e1 * inv;
    __syncwarp();
    float a0 = 0.f, a1 = 0.f;
    for (int j = 0; j < TT; j++) {
        float wj = sc[wl][j];
        const float* vp = base + j * 384 + 256 + h * 64;
        a0 += wj * vp[lane];
        a1 += wj * vp[lane + 32];
    }
    olast[b * HH + h * 64 + lane] = a0;
    olast[b * HH + h * 64 + lane + 32] = a1;
}

// ---------------- final: out-proj (last row) + MLP head ----------------
__global__ __launch_bounds__(128) void head_kernel(const float* __restrict__ olast,
                            const float* __restrict__ Wout, const float* __restrict__ bout,
                            const float* __restrict__ W1, const float* __restrict__ b1,
                            const float* __restrict__ W2, const float* __restrict__ b2,
                            float* __restrict__ pred) {
    int b = blockIdx.x;
    int j = threadIdx.x;  // 128
    __shared__ float o[HH], a[HH], hid[64];
    o[j] = olast[b * HH + j];
    __syncthreads();
    {
        float acc = bout[j];
        const float* w = Wout + (size_t)j * HH;
#pragma unroll 4
        for (int k = 0; k < HH; k++) acc += o[k] * w[k];
        a[j] = acc;
    }
    __syncthreads();
    if (j < 64) {
        float acc = b1[j];
        const float* w = W1 + (size_t)j * HH;
#pragma unroll 4
        for (int k = 0; k < HH; k++) acc += a[k] * w[k];
        hid[j] = fmaxf(acc, 0.0f);
    }
    __syncthreads();
    if (j == 0) {
        float p = b2[0];
#pragma unroll
        for (int k = 0; k < 64; k++) p += hid[k] * W2[k];
        pred[b] = p;
    }
}

// ---------------- host launch ----------------
extern "C" void kernel_launch(void* const* d_in, const int* in_sizes, int n_in,
                              void* d_out, int out_size) {
    (void)in_sizes; (void)n_in; (void)out_size;
    const float* x     = (const float*)d_in[0];
    const int*   eidx  = (const int*)d_in[1];
    const float* tseq  = (const float*)d_in[2];
    const float* W_red = (const float*)d_in[3];
    const float* b_red = (const float*)d_in[4];
    const float* s1Wl  = (const float*)d_in[5];
    const float* s1bl  = (const float*)d_in[6];
    const float* s1Wr  = (const float*)d_in[7];
    const float* s2Wl  = (const float*)d_in[8];
    const float* s2bl  = (const float*)d_in[9];
    const float* s2Wr  = (const float*)d_in[10];
    const float* Wih0  = (const float*)d_in[11];
    const float* Whh0  = (const float*)d_in[12];
    const float* bih0  = (const float*)d_in[13];
    const float* bhh0  = (const float*)d_in[14];
    const float* Wih1  = (const float*)d_in[15];
    const float* Whh1  = (const float*)d_in[16];
    const float* bih1  = (const float*)d_in[17];
    const float* bhh1  = (const float*)d_in[18];
    const float* Win   = (const float*)d_in[19];
    const float* binp  = (const float*)d_in[20];
    const float* Wout  = (const float*)d_in[21];
    const float* bout  = (const float*)d_in[22];
    const float* hW1   = (const float*)d_in[23];
    const float* hb1   = (const float*)d_in[24];
    const float* hW2   = (const float*)d_in[25];
    const float* hb2   = (const float*)d_in[26];

    float* out     = (float*)d_out;
    float* pred    = out;        // (64,1)
    float* spatial = out + BB;   // (50000,128)

    const int* src = eidx;
    const int* dst = eidx + EE;

    void* p;
    cudaGetSymbolAddress(&p, g_reduced); float* reduced = (float*)p;
    cudaGetSymbolAddress(&p, g_agg);     float* agg     = (float*)p;
    cudaGetSymbolAddress(&p, g_s);       float* sbuf    = (float*)p;
    cudaGetSymbolAddress(&p, g_invdeg);  float* invdeg  = (float*)p;
    cudaGetSymbolAddress(&p, g_deg);     int*   deg     = (int*)p;
    cudaGetSymbolAddress(&p, g_ts);      float* ts      = (float*)p;
    cudaGetSymbolAddress(&p, g_gates);   float* gates   = (float*)p;
    cudaGetSymbolAddress(&p, g_h1);      float* h1      = (float*)p;
    cudaGetSymbolAddress(&p, g_h2);      float* h2      = (float*)p;
    cudaGetSymbolAddress(&p, g_qkv);     float* qkv     = (float*)p;
    cudaGetSymbolAddress(&p, g_olast);   float* olast   = (float*)p;
    cudaGetSymbolAddress(&p, g_bias0);   float* bias0   = (float*)p;
    cudaGetSymbolAddress(&p, g_bias1);   float* bias1   = (float*)p;

    // ---- graph branch ----
    cudaMemsetAsync(agg, 0, sizeof(float) * (size_t)NND * HH);
    cudaMemsetAsync(deg, 0, sizeof(int) * NND);
    deg_kernel<<<(EE + 255) / 256, 256>>>(dst, deg, EE);
    invdeg_kernel<<<(NND + 255) / 256, 256>>>(deg, invdeg, NND);

    // reduced = x @ W_red^T + b_red
    gemm_nt_kernel<<<dim3((NND + 63) / 64, HH / 64), 256>>>(
        x, W_red, x, W_red, nullptr, b_red, reduced, NND, HH, FF, FF, 0);

    // agg += reduced[src] scattered to dst
    {
        long long tot = (long long)EE * 32;
        scatter_add_kernel<<<(unsigned)((tot + 255) / 256), 256>>>(reduced, src, dst, agg, EE);
    }
    // s = relu((agg*invdeg) @ Wl1^T + bl1 + reduced @ Wr1^T)
    gemm_nt_kernel<<<dim3((NND + 63) / 64, HH / 64), 256>>>(
        agg, s1Wl, reduced, s1Wr, invdeg, s1bl, sbuf, NND, HH, 2 * HH, HH, 1);

    cudaMemsetAsync(agg, 0, sizeof(float) * (size_t)NND * HH);
    {
        long long tot = (long long)EE * 32;
        scatter_add_kernel<<<(unsigned)((tot + 255) / 256), 256>>>(sbuf, src, dst, agg, EE);
    }
    // spatial = relu((agg*invdeg) @ Wl2^T + bl2 + s @ Wr2^T)
    gemm_nt_kernel<<<dim3((NND + 63) / 64, HH / 64), 256>>>(
        agg, s2Wl, sbuf, s2Wr, invdeg, s2bl, spatial, NND, HH, 2 * HH, HH, 1);

    // ---- temporal branch ----
    // ts = time_sequence @ W_red^T + b_red   (3200 x 128)
    gemm_nt_kernel<<<dim3((BB * TT + 63) / 64, HH / 64), 256>>>(
        tseq, W_red, tseq, W_red, nullptr, b_red, ts, BB * TT, HH, FF, FF, 0);

    bias2_kernel<<<2, 256>>>(bih0, bhh0, bias0, 4 * HH);
    bias2_kernel<<<2, 256>>>(bih1, bhh1, bias1, 4 * HH);

    // gates0 = ts @ Wih0^T + (bih0+bhh0)
    gemm_nt_kernel<<<dim3((BB * TT + 63) / 64, (4 * HH) / 64), 256>>>(
        ts, Wih0, ts, Wih0, nullptr, bias0, gates, BB * TT, 4 * HH, HH, HH, 0);
    lstm_rec_kernel<<<BB / 2, 512>>>(gates, Whh0, h1);

    // gates1 = h1 @ Wih1^T + (bih1+bhh1)
    gemm_nt_kernel<<<dim3((BB * TT + 63) / 64, (4 * HH) / 64), 256>>>(
        h1, Wih1, h1, Wih1, nullptr, bias1, gates, BB * TT, 4 * HH, HH, HH, 0);
    lstm_rec_kernel<<<BB / 2, 512>>>(gates, Whh1, h2);

    // qkv = h2 @ Win^T + bin   (3200 x 384)
    gemm_nt_kernel<<<dim3((BB * TT + 63) / 64, (3 * HH) / 64), 256>>>(
        h2, Win, h2, Win, nullptr, binp, qkv, BB * TT, 3 * HH, HH, HH, 0);

    attn_last_kernel<<<16, 256>>>(qkv, olast);
    head_kernel<<<BB, HH>>>(olast, Wout, bout, hW1, hb1, hW2, hb2, pred);
}